// round 3
// baseline (speedup 1.0000x reference)
#include <cuda_runtime.h>

// 2x trilinear upsample (TF v1 asymmetric coords, scale = 0.5 per axis).
// Input : [B=2, H=96, W=96, D=48, C=32] f32, channels-last contiguous.
// Output: [B=2, 192, 192, 96, 32] f32.
//
// Rolling-plane formulation: each thread owns one (b,h,w,c4) site and a chunk
// of DCH consecutive d cells. It keeps the 4-corner (h/h1 x w/w1) input plane
// for the current d in registers and loads only the next plane (4 float4) per
// step. Even output d-slices come straight from the current plane; odd slices
// from the plane midpoint. 8 stores + 4 loads per d cell (vs 8+8 before).

#define IN_H 96
#define IN_W 96
#define IN_D 48
#define C4   8          // 32 channels = 8 float4
#define OUT_H 192
#define OUT_W 192
#define OUT_D 96
#define DCH  6          // d cells per thread (48 % 6 == 0)

__device__ __forceinline__ float4 avg4(float4 a, float4 b) {
    return make_float4(0.5f * (a.x + b.x),
                       0.5f * (a.y + b.y),
                       0.5f * (a.z + b.z),
                       0.5f * (a.w + b.w));
}

__global__ __launch_bounds__(256)
void upsample3d_2x_kernel(const float4* __restrict__ in,
                          float4* __restrict__ out) {
    int tid = blockIdx.x * blockDim.x + threadIdx.x;
    // total threads = B * H * W * (IN_D/DCH) * C4 = 2*96*96*8*8 = 1,179,648

    int c4 = tid & (C4 - 1);
    int t  = tid >> 3;
    int dc = t % (IN_D / DCH);  t /= (IN_D / DCH);
    int w  = t % IN_W;          t /= IN_W;
    int h  = t % IN_H;
    int b  = t / IN_H;

    int h1 = min(h + 1, IN_H - 1);
    int w1 = min(w + 1, IN_W - 1);
    int d0 = dc * DCH;

    // input base pointers for the 4 (h,w) corners; d-stride = C4 float4
    const float4* i00 = in + (((b * IN_H + h ) * IN_W + w ) * IN_D) * C4 + c4;
    const float4* i01 = in + (((b * IN_H + h ) * IN_W + w1) * IN_D) * C4 + c4;
    const float4* i10 = in + (((b * IN_H + h1) * IN_W + w ) * IN_D) * C4 + c4;
    const float4* i11 = in + (((b * IN_H + h1) * IN_W + w1) * IN_D) * C4 + c4;

    // output base pointer at (b, 2h, 2w, 2*d0, c4); strides in float4 units
    const int PW = OUT_D * C4;            // +1 in output w
    const int PH = OUT_W * OUT_D * C4;    // +1 in output h
    float4* o = out + ((((b * OUT_H + 2 * h) * OUT_W + 2 * w) * OUT_D) + 2 * d0) * C4 + c4;

    // current plane (at d = d0)
    float4 a00 = i00[d0 * C4];
    float4 a01 = i01[d0 * C4];
    float4 a10 = i10[d0 * C4];
    float4 a11 = i11[d0 * C4];

#pragma unroll
    for (int k = 0; k < DCH; k++) {
        int dz = d0 + k;
        int dn = min(dz + 1, IN_D - 1);
        long ofs = (long)(2 * k) * C4;    // output d offset for this cell

        // even output d-slice: straight from current plane
        float4 p01 = avg4(a00, a01);
        float4 p10 = avg4(a00, a10);
        float4 p11 = avg4(p01, avg4(a10, a11));
        o[ofs]            = a00;
        o[ofs + PW]       = p01;
        o[ofs + PH]       = p10;
        o[ofs + PH + PW]  = p11;

        // next plane (clamped)
        float4 b00 = i00[dn * C4];
        float4 b01 = i01[dn * C4];
        float4 b10 = i10[dn * C4];
        float4 b11 = i11[dn * C4];

        // odd output d-slice: plane midpoint
        float4 m00 = avg4(a00, b00);
        float4 m01 = avg4(a01, b01);
        float4 m10 = avg4(a10, b10);
        float4 m11 = avg4(a11, b11);
        float4 q01 = avg4(m00, m01);
        float4 q10 = avg4(m00, m10);
        float4 q11 = avg4(q01, avg4(m10, m11));
        o[ofs + C4]           = m00;
        o[ofs + C4 + PW]      = q01;
        o[ofs + C4 + PH]      = q10;
        o[ofs + C4 + PH + PW] = q11;

        a00 = b00; a01 = b01; a10 = b10; a11 = b11;
    }
}

extern "C" void kernel_launch(void* const* d_in, const int* in_sizes, int n_in,
                              void* d_out, int out_size) {
    const float4* in  = (const float4*)d_in[0];
    float4*       out = (float4*)d_out;

    const int total_threads = 2 * IN_H * IN_W * (IN_D / DCH) * C4;  // 1,179,648
    const int block = 256;
    const int grid  = total_threads / block;                         // 4608 exact

    upsample3d_2x_kernel<<<grid, block>>>(in, out);
}

// round 4
// speedup vs baseline: 1.0679x; 1.0679x over previous
#include <cuda_runtime.h>

// 2x trilinear upsample (TF v1 asymmetric coords, scale = 0.5 per axis).
// Input : [B=2, H=96, W=96, D=48, C=32] f32, channels-last contiguous.
// Output: [B=2, 192, 192, 96, 32] f32.
//
// One thread = one input voxel x one float4 channel group; loads the 2x2x2
// input corner neighborhood and writes the 2x2x2 output block. Interior
// threads (96%) use pure immediate-offset addressing off two base pointers
// to keep register count <= 32 (forced by __launch_bounds__(256, 8)) so the
// SM runs 2048 threads -> max outstanding-load concurrency at the DRAM.

#define IN_H 96
#define IN_W 96
#define IN_D 48
#define C4   8          // 32 channels = 8 float4
#define OUT_H 192
#define OUT_W 192
#define OUT_D 96

// strides in float4 units (compile-time)
#define IW (IN_D * C4)          // 384    : +1 input w
#define IH (IN_W * IN_D * C4)   // 36864  : +1 input h
#define ID (C4)                 // 8      : +1 input d
#define PW (OUT_D * C4)         // 768    : +1 output w
#define PH (OUT_W * OUT_D * C4) // 147456 : +1 output h
#define PD (C4)                 // 8      : +1 output d

__device__ __forceinline__ float4 avg4(float4 a, float4 b) {
    return make_float4(0.5f * (a.x + b.x),
                       0.5f * (a.y + b.y),
                       0.5f * (a.z + b.z),
                       0.5f * (a.w + b.w));
}

__global__ __launch_bounds__(256, 8)
void upsample3d_2x_kernel(const float4* __restrict__ in,
                          float4* __restrict__ out) {
    int tid = blockIdx.x * blockDim.x + threadIdx.x;
    // total threads = B * H * W * D * C4 = 7,077,888 (exact grid)

    int c4 = tid & (C4 - 1);
    int t  = tid >> 3;
    int d  = t % IN_D;  t /= IN_D;
    int w  = t % IN_W;  t /= IN_W;
    int h  = t % IN_H;
    int b  = t / IN_H;

    const float4* p = in  + (((b * IN_H  +     h) * IN_W  +     w) * IN_D  +     d) * C4 + c4;
    float4*       o = out + (((b * OUT_H + 2 * h) * OUT_W + 2 * w) * OUT_D + 2 * d) * C4 + c4;

    if ((h < IN_H - 1) & (w < IN_W - 1) & (d < IN_D - 1)) {
        // interior: all offsets are immediates
        float4 v00 = p[0];
        float4 v01 = p[IW];
        float4 v10 = p[IH];
        float4 v11 = p[IH + IW];
        o[0]       = v00;
        o[PW]      = avg4(v00, v01);
        o[PH]      = avg4(v00, v10);
        o[PH + PW] = avg4(avg4(v00, v01), avg4(v10, v11));

        float4 m00 = avg4(v00, p[ID]);
        float4 m01 = avg4(v01, p[ID + IW]);
        float4 m10 = avg4(v10, p[ID + IH]);
        float4 m11 = avg4(v11, p[ID + IH + IW]);
        o[PD]           = m00;
        o[PD + PW]      = avg4(m00, m01);
        o[PD + PH]      = avg4(m00, m10);
        o[PD + PH + PW] = avg4(avg4(m00, m01), avg4(m10, m11));
    } else {
        // boundary: clamped (zero) offsets at the upper edges
        int dw = (w < IN_W - 1) ? IW : 0;
        int dh = (h < IN_H - 1) ? IH : 0;
        int dd = (d < IN_D - 1) ? ID : 0;

        float4 v00 = p[0];
        float4 v01 = p[dw];
        float4 v10 = p[dh];
        float4 v11 = p[dh + dw];
        o[0]       = v00;
        o[PW]      = avg4(v00, v01);
        o[PH]      = avg4(v00, v10);
        o[PH + PW] = avg4(avg4(v00, v01), avg4(v10, v11));

        float4 m00 = avg4(v00, p[dd]);
        float4 m01 = avg4(v01, p[dd + dw]);
        float4 m10 = avg4(v10, p[dd + dh]);
        float4 m11 = avg4(v11, p[dd + dh + dw]);
        o[PD]           = m00;
        o[PD + PW]      = avg4(m00, m01);
        o[PD + PH]      = avg4(m00, m10);
        o[PD + PH + PW] = avg4(avg4(m00, m01), avg4(m10, m11));
    }
}

extern "C" void kernel_launch(void* const* d_in, const int* in_sizes, int n_in,
                              void* d_out, int out_size) {
    const float4* in  = (const float4*)d_in[0];
    float4*       out = (float4*)d_out;

    const int total_threads = 2 * IN_H * IN_W * IN_D * C4;  // 7,077,888
    const int block = 256;
    const int grid  = total_threads / block;                 // 27,648 exact

    upsample3d_2x_kernel<<<grid, block>>>(in, out);
}

// round 6
// speedup vs baseline: 1.1146x; 1.0437x over previous
#include <cuda_runtime.h>
#include <cstdint>

// 2x trilinear upsample (TF v1 asymmetric coords, scale = 0.5 per axis).
// Input : [B=2, H=96, W=96, D=48, C=32] f32, channels-last contiguous.
// Output: [B=2, 192, 192, 96, 32] f32.
//
// R1 load structure (one thread = one input voxel x float4 channel group,
// 8 corner loads issued up front for max MLP), but stores are staged in SMEM
// and pushed to GMEM with 4x cp.async.bulk (12KB contiguous spans), removing
// the 8 STG.128/thread wavefront load from the L1tex pipe.
//
// Block = 384 threads = full input d-row (48) x 8 c4 groups at one (b,h,w).
// SMEM tile = [2][2][96][8] float4 = 48KB. 4 blocks/SM = 1536 threads/SM.

#define IN_H 96
#define IN_W 96
#define IN_D 48
#define C4   8
#define OUT_H 192
#define OUT_W 192
#define OUT_D 96

__device__ __forceinline__ float4 avg4(float4 a, float4 b) {
    return make_float4(0.5f * (a.x + b.x),
                       0.5f * (a.y + b.y),
                       0.5f * (a.z + b.z),
                       0.5f * (a.w + b.w));
}

__global__ __launch_bounds__(384, 4)
void upsample3d_2x_kernel(const float4* __restrict__ in,
                          float4* __restrict__ out) {
    // [ph][pw][od][c4]
    __shared__ float4 tile[2][2][OUT_D][C4];

    int bx = blockIdx.x;              // b*96*96 + h*96 + w
    int w  = bx % IN_W;
    int h  = (bx / IN_W) % IN_H;
    int b  = bx / (IN_W * IN_H);

    int tid = threadIdx.x;
    int c4  = tid & (C4 - 1);
    int d   = tid >> 3;               // 0..47

    int h1 = min(h + 1, IN_H - 1);
    int w1 = min(w + 1, IN_W - 1);
    int d1 = min(d + 1, IN_D - 1);

    auto iidx = [&](int hh, int ww, int dd) {
        return (((b * IN_H + hh) * IN_W + ww) * IN_D + dd) * C4 + c4;
    };

    // all 8 corner loads up front (MLP = 8)
    float4 v000 = in[iidx(h,  w,  d )];
    float4 v001 = in[iidx(h,  w,  d1)];
    float4 v010 = in[iidx(h,  w1, d )];
    float4 v011 = in[iidx(h,  w1, d1)];
    float4 v100 = in[iidx(h1, w,  d )];
    float4 v101 = in[iidx(h1, w,  d1)];
    float4 v110 = in[iidx(h1, w1, d )];
    float4 v111 = in[iidx(h1, w1, d1)];

    float4 m00 = avg4(v000, v001);
    float4 m01 = avg4(v010, v011);
    float4 m10 = avg4(v100, v101);
    float4 m11 = avg4(v110, v111);

    int od = 2 * d;

    // pd = 0 plane
    float4 p01 = avg4(v000, v010);
    float4 p10 = avg4(v000, v100);
    float4 p11 = avg4(p01, avg4(v100, v110));
    tile[0][0][od][c4] = v000;
    tile[0][1][od][c4] = p01;
    tile[1][0][od][c4] = p10;
    tile[1][1][od][c4] = p11;

    // pd = 1 plane
    float4 q01 = avg4(m00, m01);
    float4 q10 = avg4(m00, m10);
    float4 q11 = avg4(q01, avg4(m10, m11));
    tile[0][0][od + 1][c4] = m00;
    tile[0][1][od + 1][c4] = q01;
    tile[1][0][od + 1][c4] = q10;
    tile[1][1][od + 1][c4] = q11;

    __syncthreads();

    if (tid == 0) {
        // order generic-proxy STS before async-proxy bulk copy reads
        asm volatile("fence.proxy.async.shared::cta;" ::: "memory");

        int oh = 2 * h, ow = 2 * w;
        const int SPAN = OUT_D * C4 * (int)sizeof(float4);   // 12288 bytes

        #pragma unroll
        for (int ph = 0; ph < 2; ph++) {
            #pragma unroll
            for (int pw = 0; pw < 2; pw++) {
                float4* dst = out + (((size_t)(b * OUT_H + oh + ph) * OUT_W
                                      + (ow + pw)) * OUT_D) * C4;
                unsigned int src =
                    (unsigned int)__cvta_generic_to_shared(&tile[ph][pw][0][0]);
                asm volatile(
                    "cp.async.bulk.global.shared::cta.bulk_group [%0], [%1], %2;"
                    :: "l"(dst), "r"(src), "r"(SPAN) : "memory");
            }
        }
        asm volatile("cp.async.bulk.commit_group;" ::: "memory");
        // smem is reused by the next block on this SM: must drain before exit
        asm volatile("cp.async.bulk.wait_group 0;" ::: "memory");
    }
    __syncthreads();
}

extern "C" void kernel_launch(void* const* d_in, const int* in_sizes, int n_in,
                              void* d_out, int out_size) {
    const float4* in  = (const float4*)d_in[0];
    float4*       out = (float4*)d_out;

    const int grid  = 2 * IN_H * IN_W;   // 18432 blocks, one per (b,h,w)
    const int block = IN_D * C4;          // 384 threads

    upsample3d_2x_kernel<<<grid, block>>>(in, out);
}